// round 3
// baseline (speedup 1.0000x reference)
#include <cuda_runtime.h>
#include <cuda_bf16.h>
#include <cstdint>

#define BATCH 8
#define NNODE 2048
#define FEAT  128

// ---------------- device scratch (no allocations allowed) -------------------
__device__ __nv_bfloat16 g_wht_h[BATCH * FEAT * NNODE];  // WhT hi, [b][f][n]
__device__ __nv_bfloat16 g_wht_l[BATCH * FEAT * NNODE];  // WhT lo
__device__ float g_wh1[BATCH * NNODE];
__device__ float g_wh2[BATCH * NNODE];
__device__ float g_wh2max[BATCH];

// ---------------- helpers ---------------------------------------------------
__device__ __forceinline__ float leakyf(float x) { return fmaxf(x, 0.2f * x); }

__device__ __forceinline__ void atomicMaxF(float* a, float v) {
    int old = __float_as_int(*a);
    while (__int_as_float(old) < v) {
        int assumed = old;
        old = atomicCAS((int*)a, assumed, __float_as_int(v));
        if (old == assumed) break;
    }
}

__device__ __forceinline__ uint32_t smem_u32(const void* p) {
    uint32_t a;
    asm("{ .reg .u64 t; cvta.to.shared.u64 t, %1; cvt.u32.u64 %0, t; }"
        : "=r"(a) : "l"(p));
    return a;
}

__device__ __forceinline__ uint32_t pack_bf2(float x, float y) {
    __nv_bfloat162 v = __floats2bfloat162_rn(x, y);
    return *reinterpret_cast<uint32_t*>(&v);
}

#define LDSM4(r, a)                                                            \
    asm volatile(                                                              \
        "ldmatrix.sync.aligned.m8n8.x4.shared.b16 {%0,%1,%2,%3}, [%4];"        \
        : "=r"((r)[0]), "=r"((r)[1]), "=r"((r)[2]), "=r"((r)[3])               \
        : "r"(a))

#define MMA16816(c, A, B0, B1)                                                 \
    asm volatile(                                                              \
        "mma.sync.aligned.m16n8k16.row.col.f32.bf16.bf16.f32 "                 \
        "{%0,%1,%2,%3}, {%4,%5,%6,%7}, {%8,%9}, {%0,%1,%2,%3};"                \
        : "+f"((c)[0]), "+f"((c)[1]), "+f"((c)[2]), "+f"((c)[3])               \
        : "r"((A)[0]), "r"((A)[1]), "r"((A)[2]), "r"((A)[3]),                  \
          "r"(B0), "r"(B1))

// ============================================================================
// k_init
// ============================================================================
__global__ void k_init() {
    if (threadIdx.x < BATCH) g_wh2max[threadIdx.x] = -1e30f;
}

// ============================================================================
// k_linear: Wh = h @ W^T + b (fp32 scalar). Emits WhT hi/lo bf16 (f-major),
// Wh1/Wh2 (fp32), per-batch max(Wh2).
// grid (16, 8), 256 threads, per block: 128 rows x 128 feats of one batch.
// ============================================================================
__global__ __launch_bounds__(256, 1) void k_linear(
    const float* __restrict__ h, const float* __restrict__ W,
    const float* __restrict__ Wb, const float* __restrict__ aw) {
    __shared__ float h_s[128 * 33];
    __shared__ float wt_s[32 * 132];
    __shared__ float mx_s[16];

    const int b = blockIdx.y;
    const int n0 = blockIdx.x * 128;
    const int t = threadIdx.x;
    const int tx = t & 15, ty = t >> 4;
    const int lid = t & 31, w = t >> 5;
    const int r0 = ty * 8, f0 = tx * 8;

    float acc[8][8];
#pragma unroll
    for (int u = 0; u < 8; u++)
#pragma unroll
        for (int v = 0; v < 8; v++) acc[u][v] = 0.f;

    for (int kc = 0; kc < 4; kc++) {
        const int k0 = kc * 32;
        __syncthreads();
#pragma unroll
        for (int i = 0; i < 4; i++) {
            int idx = t + i * 256;  // 0..1023 float4s
            int row = idx >> 3;
            int c4 = (idx & 7) * 4;
            float4 hv = *(const float4*)&h[((size_t)(b * NNODE + n0 + row)) * FEAT + k0 + c4];
            h_s[row * 33 + c4 + 0] = hv.x;
            h_s[row * 33 + c4 + 1] = hv.y;
            h_s[row * 33 + c4 + 2] = hv.z;
            h_s[row * 33 + c4 + 3] = hv.w;
            float4 wv = *(const float4*)&W[(size_t)row * FEAT + k0 + c4];
            wt_s[(c4 + 0) * 132 + row] = wv.x;
            wt_s[(c4 + 1) * 132 + row] = wv.y;
            wt_s[(c4 + 2) * 132 + row] = wv.z;
            wt_s[(c4 + 3) * 132 + row] = wv.w;
        }
        __syncthreads();

#pragma unroll 4
        for (int k = 0; k < 32; k++) {
            float4 b0 = *(const float4*)&wt_s[k * 132 + f0];
            float4 b1 = *(const float4*)&wt_s[k * 132 + f0 + 4];
            float bb[8] = {b0.x, b0.y, b0.z, b0.w, b1.x, b1.y, b1.z, b1.w};
#pragma unroll
            for (int u = 0; u < 8; u++) {
                float a = h_s[(r0 + u) * 33 + k];
#pragma unroll
                for (int v = 0; v < 8; v++) acc[u][v] = fmaf(a, bb[v], acc[u][v]);
            }
        }
    }

    float a1[8], a2[8];
#pragma unroll
    for (int v = 0; v < 8; v++) {
        float bias = Wb[f0 + v];
        a1[v] = aw[f0 + v];
        a2[v] = aw[FEAT + f0 + v];
#pragma unroll
        for (int u = 0; u < 8; u++) acc[u][v] += bias;
    }

    // WhT hi/lo stores (bf16, f-major, n contiguous)
#pragma unroll
    for (int v = 0; v < 8; v++) {
        float hi_f[8], lo_f[8];
#pragma unroll
        for (int u = 0; u < 8; u++) {
            float x = acc[u][v];
            float hf = __bfloat162float(__float2bfloat16_rn(x));
            hi_f[u] = hf;
            lo_f[u] = x - hf;
        }
        uint4 ph, pl;
        ph.x = pack_bf2(hi_f[0], hi_f[1]); ph.y = pack_bf2(hi_f[2], hi_f[3]);
        ph.z = pack_bf2(hi_f[4], hi_f[5]); ph.w = pack_bf2(hi_f[6], hi_f[7]);
        pl.x = pack_bf2(lo_f[0], lo_f[1]); pl.y = pack_bf2(lo_f[2], lo_f[3]);
        pl.z = pack_bf2(lo_f[4], lo_f[5]); pl.w = pack_bf2(lo_f[6], lo_f[7]);
        size_t ob = ((size_t)(b * FEAT + f0 + v)) * NNODE + n0 + r0;
        *(uint4*)&g_wht_h[ob] = ph;
        *(uint4*)&g_wht_l[ob] = pl;
    }

    // Wh1/Wh2 per row + block max of Wh2
    float m2 = -1e30f;
#pragma unroll
    for (int u = 0; u < 8; u++) {
        float p1 = 0.f, p2 = 0.f;
#pragma unroll
        for (int v = 0; v < 8; v++) {
            p1 = fmaf(a1[v], acc[u][v], p1);
            p2 = fmaf(a2[v], acc[u][v], p2);
        }
#pragma unroll
        for (int off = 8; off >= 1; off >>= 1) {
            p1 += __shfl_xor_sync(0xffffffffu, p1, off);
            p2 += __shfl_xor_sync(0xffffffffu, p2, off);
        }
        if ((lid & 15) == 0) {
            g_wh1[b * NNODE + n0 + r0 + u] = p1;
            g_wh2[b * NNODE + n0 + r0 + u] = p2;
            m2 = fmaxf(m2, p2);
        }
    }
    if ((lid & 15) == 0) mx_s[w * 2 + (lid >> 4)] = m2;
    __syncthreads();
    if (t == 0) {
        float m = mx_s[0];
#pragma unroll
        for (int i = 1; i < 16; i++) m = fmaxf(m, mx_s[i]);
        atomicMaxF(&g_wh2max[b], m);
    }
}

// ============================================================================
// k_attn: per CTA = 128 query rows of one batch, all 128 output features.
// 8 warps, each owns 16 rows with full-width fp32 register accumulators.
// Per 128-key chunk: P tile (fp32 -> bf16 hi/lo) + WhT chunk (bf16 hi/lo)
// into swizzled SMEM, then ldmatrix + mma.sync m16n8k16 (3-product bf16x3).
// Epilogue: /rowsum, LayerNorm, leaky.
// SMEM tile layout: [rows][256B row], 16B chunk index ^= (row & 7).
// ============================================================================
static constexpr int TILE_B = 32768;  // 128 rows x 256 bytes
static constexpr int ATTN_SMEM = 1024 + 4 * TILE_B;

__global__ __launch_bounds__(256, 1) void k_attn(const int* __restrict__ adj,
                                                 float* __restrict__ out) {
    extern __shared__ __align__(16) char dyn[];
    float* rowsum = (float*)dyn;       // 512B used, 1024 reserved
    char* ahi = dyn + 1024;
    char* alo = ahi + TILE_B;
    char* bhi = alo + TILE_B;
    char* blo = bhi + TILE_B;

    const int t = threadIdx.x;
    const int wid = t >> 5, lane = t & 31;
    const int b = blockIdx.x >> 4;
    const int n0 = (blockIdx.x & 15) << 7;

    if (t < 128) rowsum[t] = 0.f;
    __syncthreads();

    // per-warp row constants
    float w1v[16];
#pragma unroll
    for (int rr = 0; rr < 16; rr++)
        w1v[rr] = g_wh1[b * NNODE + n0 + wid * 16 + rr];
    const float mx = g_wh2max[b];

    // accumulators: warp rows [wid*16, +16), 16 n-tiles of 8 cols
    float acc[16][4];
#pragma unroll
    for (int nt = 0; nt < 16; nt++)
#pragma unroll
        for (int q = 0; q < 4; q++) acc[nt][q] = 0.f;

    // ldmatrix per-lane bases
    const uint32_t ahi_a = smem_u32(ahi), alo_a = smem_u32(alo);
    const uint32_t bhi_a = smem_u32(bhi), blo_a = smem_u32(blo);
    const int a_row = wid * 16 + (lane & 7) + ((lane >> 3) & 1) * 8;
    const uint32_t a_hk = lane >> 4;         // 16B half along k
    const uint32_t a_sw = lane & 7;
    const uint32_t aoff = (uint32_t)a_row * 256u;
    const int b_row_off = ((lane >> 4) & 1) * 8 + (lane & 7);
    const uint32_t b_hk = (lane >> 3) & 1;
    const uint32_t b_sw = lane & 7;
    const uint32_t boff = (uint32_t)b_row_off * 256u;

    // P-store per-lane constants: lane covers j = lane*4..+3 for each row
    const uint32_t p_chunk = (uint32_t)(lane >> 1);  // 16B chunk pre-swizzle
    const uint32_t p_half = (uint32_t)(lane & 1) * 8;
    // B-store: lane covers 8 j (16B)
    const int jj = (lane & 15) * 8;
    const int bhalf = lane >> 4;

#pragma unroll 1
    for (int c = 0; c < 16; c++) {
        const int j0 = c * 128;
        if (c) __syncthreads();  // previous chunk's MMAs done

        // ---- B tiles: WhT hi/lo chunk [128 f][128 j] ----
#pragma unroll
        for (int it = 0; it < 8; it++) {
            int f = wid * 16 + it * 2 + bhalf;
            size_t gb = ((size_t)(b * FEAT + f)) * NNODE + j0 + jj;
            uint4 vh = *(const uint4*)&g_wht_h[gb];
            uint4 vl = *(const uint4*)&g_wht_l[gb];
            uint32_t so = (uint32_t)f * 256u +
                          ((((uint32_t)(lane & 15)) ^ (uint32_t)(f & 7)) << 4);
            *(uint4*)(bhi + so) = vh;
            *(uint4*)(blo + so) = vl;
        }

        // ---- P tiles: rows wid*16..+15, lane covers j = lane*4..+3 ----
        const float4 w2v = *(const float4*)&g_wh2[b * NNODE + j0 + lane * 4];
#pragma unroll
        for (int rr = 0; rr < 16; rr++) {
            int r = wid * 16 + rr;
            float w1 = w1v[rr];
            float Mr = leakyf(w1 + mx);
            const int4 av = *(const int4*)&adj[((size_t)(b * NNODE + n0 + r)) * NNODE + j0 + lane * 4];
            float p0 = av.x ? __expf(leakyf(w1 + w2v.x) - Mr) : 0.f;
            float p1 = av.y ? __expf(leakyf(w1 + w2v.y) - Mr) : 0.f;
            float p2 = av.z ? __expf(leakyf(w1 + w2v.z) - Mr) : 0.f;
            float p3 = av.w ? __expf(leakyf(w1 + w2v.w) - Mr) : 0.f;

            __nv_bfloat162 h01 = __floats2bfloat162_rn(p0, p1);
            __nv_bfloat162 h23 = __floats2bfloat162_rn(p2, p3);
            float l0 = p0 - __low2float(h01), l1 = p1 - __high2float(h01);
            float l2 = p2 - __low2float(h23), l3 = p3 - __high2float(h23);
            uint2 uh = make_uint2(*(uint32_t*)&h01, *(uint32_t*)&h23);
            uint2 ul = make_uint2(pack_bf2(l0, l1), pack_bf2(l2, l3));
            uint32_t so = (uint32_t)r * 256u +
                          ((p_chunk ^ (uint32_t)(r & 7)) << 4) + p_half;
            *(uint2*)(ahi + so) = uh;
            *(uint2*)(alo + so) = ul;

            float s = p0 + p1 + p2 + p3;
#pragma unroll
            for (int o = 16; o >= 1; o >>= 1)
                s += __shfl_xor_sync(0xffffffffu, s, o);
            if (lane == 0) rowsum[r] += s;
        }

        __syncthreads();  // tiles visible

        // ---- MMA: 8 k-steps x 16 n-tiles x 3 products ----
#pragma unroll 1
        for (int kk = 0; kk < 8; kk++) {
            uint32_t ah[4], al[4];
            uint32_t ca = (((uint32_t)(kk * 2) + a_hk) ^ a_sw) << 4;
            LDSM4(ah, ahi_a + aoff + ca);
            LDSM4(al, alo_a + aoff + ca);
            uint32_t cb = (((uint32_t)(kk * 2) + b_hk) ^ b_sw) << 4;
#pragma unroll
            for (int ntp = 0; ntp < 8; ntp++) {
                uint32_t bh[4], bl[4];
                uint32_t bo = boff + (uint32_t)ntp * 4096u + cb;
                LDSM4(bh, bhi_a + bo);
                LDSM4(bl, blo_a + bo);
                MMA16816(acc[ntp * 2], ah, bh[0], bh[1]);
                MMA16816(acc[ntp * 2], al, bh[0], bh[1]);
                MMA16816(acc[ntp * 2], ah, bl[0], bl[1]);
                MMA16816(acc[ntp * 2 + 1], ah, bh[2], bh[3]);
                MMA16816(acc[ntp * 2 + 1], al, bh[2], bh[3]);
                MMA16816(acc[ntp * 2 + 1], ah, bl[2], bl[3]);
            }
        }
    }

    // ---- epilogue ----
    const int g = lane >> 2, q = lane & 3;
    const int rA = wid * 16 + g, rB = rA + 8;
    const float invA = 1.f / rowsum[rA];
    const float invB = 1.f / rowsum[rB];

    float vA[32], vB[32];
    float sA = 0.f, qA = 0.f, sB = 0.f, qB = 0.f;
#pragma unroll
    for (int nt = 0; nt < 16; nt++) {
        float a0 = acc[nt][0] * invA, a1 = acc[nt][1] * invA;
        float b0 = acc[nt][2] * invB, b1 = acc[nt][3] * invB;
        vA[nt * 2] = a0; vA[nt * 2 + 1] = a1;
        vB[nt * 2] = b0; vB[nt * 2 + 1] = b1;
        sA += a0 + a1; qA = fmaf(a0, a0, fmaf(a1, a1, qA));
        sB += b0 + b1; qB = fmaf(b0, b0, fmaf(b1, b1, qB));
    }
#pragma unroll
    for (int o = 2; o >= 1; o >>= 1) {
        sA += __shfl_xor_sync(0xffffffffu, sA, o);
        qA += __shfl_xor_sync(0xffffffffu, qA, o);
        sB += __shfl_xor_sync(0xffffffffu, sB, o);
        qB += __shfl_xor_sync(0xffffffffu, qB, o);
    }
    const float muA = sA * (1.f / 128.f);
    const float muB = sB * (1.f / 128.f);
    const float rsA = rsqrtf(qA * (1.f / 128.f) - muA * muA + 1e-5f);
    const float rsB = rsqrtf(qB * (1.f / 128.f) - muB * muB + 1e-5f);

    float* oA = out + ((size_t)(b * NNODE + n0 + rA)) * FEAT;
    float* oB = out + ((size_t)(b * NNODE + n0 + rB)) * FEAT;
#pragma unroll
    for (int nt = 0; nt < 16; nt++) {
        float zA0 = (vA[nt * 2] - muA) * rsA, zA1 = (vA[nt * 2 + 1] - muA) * rsA;
        float zB0 = (vB[nt * 2] - muB) * rsB, zB1 = (vB[nt * 2 + 1] - muB) * rsB;
        *(float2*)&oA[nt * 8 + q * 2] = make_float2(leakyf(zA0), leakyf(zA1));
        *(float2*)&oB[nt * 8 + q * 2] = make_float2(leakyf(zB0), leakyf(zB1));
    }
}

// ============================================================================
extern "C" void kernel_launch(void* const* d_in, const int* in_sizes, int n_in,
                              void* d_out, int out_size) {
    const float* h   = (const float*)d_in[0];
    const int*   adj = (const int*)d_in[1];
    const float* Ww  = (const float*)d_in[2];
    const float* Wb  = (const float*)d_in[3];
    const float* aw  = (const float*)d_in[4];
    float* out = (float*)d_out;

    k_init<<<1, 32>>>();
    k_linear<<<dim3(16, 8), 256>>>(h, Ww, Wb, aw);
    cudaFuncSetAttribute(k_attn, cudaFuncAttributeMaxDynamicSharedMemorySize,
                         ATTN_SMEM);
    k_attn<<<128, 256, ATTN_SMEM>>>(adj, out);
}

// round 4
// speedup vs baseline: 2.2651x; 2.2651x over previous
#include <cuda_runtime.h>
#include <cuda_bf16.h>
#include <cuda_fp16.h>
#include <cstdint>

#define BATCH 8
#define NNODE 2048
#define FEAT  128

// ---------------- device scratch (no allocations allowed) -------------------
__device__ __half g_wht[BATCH * FEAT * NNODE];  // WhT fp16, [b][f][n]
__device__ float g_wh1[BATCH * NNODE];
__device__ float g_wh2[BATCH * NNODE];
__device__ float g_wh2max[BATCH];

// ---------------- helpers ---------------------------------------------------
__device__ __forceinline__ float leakyf(float x) { return fmaxf(x, 0.2f * x); }

__device__ __forceinline__ float ex2f(float x) {
    float r;
    asm("ex2.approx.ftz.f32 %0, %1;" : "=f"(r) : "f"(x));
    return r;
}

__device__ __forceinline__ void atomicMaxF(float* a, float v) {
    int old = __float_as_int(*a);
    while (__int_as_float(old) < v) {
        int assumed = old;
        old = atomicCAS((int*)a, assumed, __float_as_int(v));
        if (old == assumed) break;
    }
}

__device__ __forceinline__ uint32_t smem_u32(const void* p) {
    uint32_t a;
    asm("{ .reg .u64 t; cvta.to.shared.u64 t, %1; cvt.u32.u64 %0, t; }"
        : "=r"(a) : "l"(p));
    return a;
}

__device__ __forceinline__ uint32_t pack_h2(float x, float y) {
    __half2 v = __floats2half2_rn(x, y);
    return *reinterpret_cast<uint32_t*>(&v);
}

#define LDSM4(r, a)                                                            \
    asm volatile(                                                              \
        "ldmatrix.sync.aligned.m8n8.x4.shared.b16 {%0,%1,%2,%3}, [%4];"        \
        : "=r"((r)[0]), "=r"((r)[1]), "=r"((r)[2]), "=r"((r)[3])               \
        : "r"(a))

#define MMA16816(c, A, B0, B1)                                                 \
    asm volatile(                                                              \
        "mma.sync.aligned.m16n8k16.row.col.f32.f16.f16.f32 "                   \
        "{%0,%1,%2,%3}, {%4,%5,%6,%7}, {%8,%9}, {%0,%1,%2,%3};"                \
        : "+f"((c)[0]), "+f"((c)[1]), "+f"((c)[2]), "+f"((c)[3])               \
        : "r"((A)[0]), "r"((A)[1]), "r"((A)[2]), "r"((A)[3]),                  \
          "r"(B0), "r"(B1))

// ============================================================================
// k_init
// ============================================================================
__global__ void k_init() {
    if (threadIdx.x < BATCH) g_wh2max[threadIdx.x] = -1e30f;
}

// ============================================================================
// k_linear: Wh = h @ W^T + b (fp32 scalar). Emits WhT fp16 (f-major),
// Wh1/Wh2 (fp32), per-batch max(Wh2).
// grid (16, 8), 256 threads, per block: 128 rows x 128 feats of one batch.
// ============================================================================
__global__ __launch_bounds__(256, 1) void k_linear(
    const float* __restrict__ h, const float* __restrict__ W,
    const float* __restrict__ Wb, const float* __restrict__ aw) {
    __shared__ float h_s[128 * 33];
    __shared__ float wt_s[32 * 132];
    __shared__ float mx_s[16];

    const int b = blockIdx.y;
    const int n0 = blockIdx.x * 128;
    const int t = threadIdx.x;
    const int tx = t & 15, ty = t >> 4;
    const int lid = t & 31, w = t >> 5;
    const int r0 = ty * 8, f0 = tx * 8;

    float acc[8][8];
#pragma unroll
    for (int u = 0; u < 8; u++)
#pragma unroll
        for (int v = 0; v < 8; v++) acc[u][v] = 0.f;

    for (int kc = 0; kc < 4; kc++) {
        const int k0 = kc * 32;
        __syncthreads();
#pragma unroll
        for (int i = 0; i < 4; i++) {
            int idx = t + i * 256;  // 0..1023 float4s
            int row = idx >> 3;
            int c4 = (idx & 7) * 4;
            float4 hv = *(const float4*)&h[((size_t)(b * NNODE + n0 + row)) * FEAT + k0 + c4];
            h_s[row * 33 + c4 + 0] = hv.x;
            h_s[row * 33 + c4 + 1] = hv.y;
            h_s[row * 33 + c4 + 2] = hv.z;
            h_s[row * 33 + c4 + 3] = hv.w;
            float4 wv = *(const float4*)&W[(size_t)row * FEAT + k0 + c4];
            wt_s[(c4 + 0) * 132 + row] = wv.x;
            wt_s[(c4 + 1) * 132 + row] = wv.y;
            wt_s[(c4 + 2) * 132 + row] = wv.z;
            wt_s[(c4 + 3) * 132 + row] = wv.w;
        }
        __syncthreads();

#pragma unroll 4
        for (int k = 0; k < 32; k++) {
            float4 b0 = *(const float4*)&wt_s[k * 132 + f0];
            float4 b1 = *(const float4*)&wt_s[k * 132 + f0 + 4];
            float bb[8] = {b0.x, b0.y, b0.z, b0.w, b1.x, b1.y, b1.z, b1.w};
#pragma unroll
            for (int u = 0; u < 8; u++) {
                float a = h_s[(r0 + u) * 33 + k];
#pragma unroll
                for (int v = 0; v < 8; v++) acc[u][v] = fmaf(a, bb[v], acc[u][v]);
            }
        }
    }

    float a1[8], a2[8];
#pragma unroll
    for (int v = 0; v < 8; v++) {
        float bias = Wb[f0 + v];
        a1[v] = aw[f0 + v];
        a2[v] = aw[FEAT + f0 + v];
#pragma unroll
        for (int u = 0; u < 8; u++) acc[u][v] += bias;
    }

    // WhT fp16 stores (f-major, n contiguous): per v, 8 rows = 16B
#pragma unroll
    for (int v = 0; v < 8; v++) {
        uint4 ph;
        ph.x = pack_h2(acc[0][v], acc[1][v]);
        ph.y = pack_h2(acc[2][v], acc[3][v]);
        ph.z = pack_h2(acc[4][v], acc[5][v]);
        ph.w = pack_h2(acc[6][v], acc[7][v]);
        size_t ob = ((size_t)(b * FEAT + f0 + v)) * NNODE + n0 + r0;
        *(uint4*)&g_wht[ob] = ph;
    }

    // Wh1/Wh2 per row + block max of Wh2
    float m2 = -1e30f;
#pragma unroll
    for (int u = 0; u < 8; u++) {
        float p1 = 0.f, p2 = 0.f;
#pragma unroll
        for (int v = 0; v < 8; v++) {
            p1 = fmaf(a1[v], acc[u][v], p1);
            p2 = fmaf(a2[v], acc[u][v], p2);
        }
#pragma unroll
        for (int off = 8; off >= 1; off >>= 1) {
            p1 += __shfl_xor_sync(0xffffffffu, p1, off);
            p2 += __shfl_xor_sync(0xffffffffu, p2, off);
        }
        if ((lid & 15) == 0) {
            g_wh1[b * NNODE + n0 + r0 + u] = p1;
            g_wh2[b * NNODE + n0 + r0 + u] = p2;
            m2 = fmaxf(m2, p2);
        }
    }
    if ((lid & 15) == 0) mx_s[w * 2 + (lid >> 4)] = m2;
    __syncthreads();
    if (t == 0) {
        float m = mx_s[0];
#pragma unroll
        for (int i = 1; i < 16; i++) m = fmaxf(m, mx_s[i]);
        atomicMaxF(&g_wh2max[b], m);
    }
}

// ============================================================================
// k_attn: per CTA = 128 query rows of one batch, all 128 output features.
// 8 warps, each owns 16 rows with full-width fp32 register accumulators.
// Per 128-key chunk: P tile (fp32 -> fp16) + WhT chunk (fp16) into swizzled
// SMEM, then ldmatrix + mma.sync m16n8k16 fp16 (single product).
// Epilogue: /rowsum, LayerNorm, leaky.
// SMEM tile layout: [rows][256B row], 16B chunk index ^= (row & 7).
// ============================================================================
static constexpr int TILE_B = 32768;  // 128 rows x 256 bytes
static constexpr int ATTN_SMEM = 1024 + 2 * TILE_B;
#define LOG2E 1.4426950408889634f

__global__ __launch_bounds__(256, 1) void k_attn(const int* __restrict__ adj,
                                                 float* __restrict__ out) {
    extern __shared__ __align__(16) char dyn[];
    float* rowsum = (float*)dyn;  // 512B used, 1024 reserved
    char* atile = dyn + 1024;
    char* btile = atile + TILE_B;

    const int t = threadIdx.x;
    const int wid = t >> 5, lane = t & 31;
    const int b = blockIdx.x >> 4;
    const int n0 = (blockIdx.x & 15) << 7;

    // per-warp row constants (row = wid*16 + rr)
    float w1v[16], mrl[16];
    const float mx = g_wh2max[b];
#pragma unroll
    for (int rr = 0; rr < 16; rr++) {
        float w1 = g_wh1[b * NNODE + n0 + wid * 16 + rr];
        w1v[rr] = w1;
        mrl[rr] = -leakyf(w1 + mx) * LOG2E;
    }

    // accumulators: warp rows [wid*16, +16), 16 n-tiles of 8 cols
    float acc[16][4];
#pragma unroll
    for (int nt = 0; nt < 16; nt++)
#pragma unroll
        for (int q = 0; q < 4; q++) acc[nt][q] = 0.f;
    float s_acc[16];
#pragma unroll
    for (int rr = 0; rr < 16; rr++) s_acc[rr] = 0.f;

    // ldmatrix per-lane bases
    const uint32_t atile_a = smem_u32(atile), btile_a = smem_u32(btile);
    const int a_row = wid * 16 + (lane & 7) + ((lane >> 3) & 1) * 8;
    const uint32_t a_hk = lane >> 4;  // 16B half along k
    const uint32_t a_sw = lane & 7;
    const uint32_t aoff = (uint32_t)a_row * 256u;
    const int b_row_off = ((lane >> 4) & 1) * 8 + (lane & 7);
    const uint32_t b_hk = (lane >> 3) & 1;
    const uint32_t b_sw = lane & 7;
    const uint32_t boff = (uint32_t)b_row_off * 256u;

    // P-store per-lane constants: lane covers j = lane*4..+3 for each row
    const uint32_t p_chunk = (uint32_t)(lane >> 1);  // 16B chunk pre-swizzle
    const uint32_t p_half = (uint32_t)(lane & 1) * 8;
    // B-store: lane covers 8 j (16B)
    const int jj = (lane & 15) * 8;
    const int bhalf = lane >> 4;

#pragma unroll 1
    for (int c = 0; c < 16; c++) {
        const int j0 = c * 128;
        if (c) __syncthreads();  // previous chunk's MMAs done

        // ---- B tile: WhT chunk [128 f][128 j] fp16 ----
#pragma unroll
        for (int it = 0; it < 8; it++) {
            int f = wid * 16 + it * 2 + bhalf;
            size_t gb = ((size_t)(b * FEAT + f)) * NNODE + j0 + jj;
            uint4 vh = *(const uint4*)&g_wht[gb];
            uint32_t so = (uint32_t)f * 256u +
                          ((((uint32_t)(lane & 15)) ^ (uint32_t)(f & 7)) << 4);
            *(uint4*)(btile + so) = vh;
        }

        // ---- P tile: rows wid*16..+15, lane covers j = lane*4..+3 ----
        const float4 w2v = *(const float4*)&g_wh2[b * NNODE + j0 + lane * 4];
#pragma unroll
        for (int rr = 0; rr < 16; rr++) {
            int r = wid * 16 + rr;
            const float w1 = w1v[rr];
            const float ml = mrl[rr];
            const int4 av = *(const int4*)&adj[((size_t)(b * NNODE + n0 + r)) * NNODE + j0 + lane * 4];
            float t0 = w1 + w2v.x, t1 = w1 + w2v.y;
            float t2 = w1 + w2v.z, t3 = w1 + w2v.w;
            float p0 = av.x ? ex2f(fmaf(fmaxf(t0, 0.2f * t0), LOG2E, ml)) : 0.f;
            float p1 = av.y ? ex2f(fmaf(fmaxf(t1, 0.2f * t1), LOG2E, ml)) : 0.f;
            float p2 = av.z ? ex2f(fmaf(fmaxf(t2, 0.2f * t2), LOG2E, ml)) : 0.f;
            float p3 = av.w ? ex2f(fmaf(fmaxf(t3, 0.2f * t3), LOG2E, ml)) : 0.f;

            uint2 uh = make_uint2(pack_h2(p0, p1), pack_h2(p2, p3));
            uint32_t so = (uint32_t)r * 256u +
                          ((p_chunk ^ (uint32_t)(r & 7)) << 4) + p_half;
            *(uint2*)(atile + so) = uh;
            s_acc[rr] += (p0 + p1) + (p2 + p3);
        }

        __syncthreads();  // tiles visible

        // ---- MMA: 8 k-steps x 8 n-tile-pairs ----
#pragma unroll 1
        for (int kk = 0; kk < 8; kk++) {
            uint32_t ah[4];
            uint32_t ca = (((uint32_t)(kk * 2) + a_hk) ^ a_sw) << 4;
            LDSM4(ah, atile_a + aoff + ca);
            uint32_t cb = (((uint32_t)(kk * 2) + b_hk) ^ b_sw) << 4;
#pragma unroll
            for (int ntp = 0; ntp < 8; ntp++) {
                uint32_t bh[4];
                LDSM4(bh, btile_a + boff + (uint32_t)ntp * 4096u + cb);
                MMA16816(acc[ntp * 2], ah, bh[0], bh[1]);
                MMA16816(acc[ntp * 2 + 1], ah, bh[2], bh[3]);
            }
        }
    }

    // ---- rowsum reduction (once, not per chunk) ----
#pragma unroll
    for (int rr = 0; rr < 16; rr++) {
        float s = s_acc[rr];
#pragma unroll
        for (int o = 16; o >= 1; o >>= 1)
            s += __shfl_xor_sync(0xffffffffu, s, o);
        if (lane == 0) rowsum[wid * 16 + rr] = s;
    }
    __syncwarp();

    // ---- epilogue ----
    const int g = lane >> 2, q = lane & 3;
    const int rA = wid * 16 + g, rB = rA + 8;
    const float invA = 1.f / rowsum[rA];
    const float invB = 1.f / rowsum[rB];

    float vA[32], vB[32];
    float sA = 0.f, qA = 0.f, sB = 0.f, qB = 0.f;
#pragma unroll
    for (int nt = 0; nt < 16; nt++) {
        float a0 = acc[nt][0] * invA, a1 = acc[nt][1] * invA;
        float b0 = acc[nt][2] * invB, b1 = acc[nt][3] * invB;
        vA[nt * 2] = a0; vA[nt * 2 + 1] = a1;
        vB[nt * 2] = b0; vB[nt * 2 + 1] = b1;
        sA += a0 + a1; qA = fmaf(a0, a0, fmaf(a1, a1, qA));
        sB += b0 + b1; qB = fmaf(b0, b0, fmaf(b1, b1, qB));
    }
#pragma unroll
    for (int o = 2; o >= 1; o >>= 1) {
        sA += __shfl_xor_sync(0xffffffffu, sA, o);
        qA += __shfl_xor_sync(0xffffffffu, qA, o);
        sB += __shfl_xor_sync(0xffffffffu, sB, o);
        qB += __shfl_xor_sync(0xffffffffu, qB, o);
    }
    const float muA = sA * (1.f / 128.f);
    const float muB = sB * (1.f / 128.f);
    const float rsA = rsqrtf(qA * (1.f / 128.f) - muA * muA + 1e-5f);
    const float rsB = rsqrtf(qB * (1.f / 128.f) - muB * muB + 1e-5f);

    float* oA = out + ((size_t)(b * NNODE + n0 + rA)) * FEAT;
    float* oB = out + ((size_t)(b * NNODE + n0 + rB)) * FEAT;
#pragma unroll
    for (int nt = 0; nt < 16; nt++) {
        float zA0 = (vA[nt * 2] - muA) * rsA, zA1 = (vA[nt * 2 + 1] - muA) * rsA;
        float zB0 = (vB[nt * 2] - muB) * rsB, zB1 = (vB[nt * 2 + 1] - muB) * rsB;
        *(float2*)&oA[nt * 8 + q * 2] = make_float2(leakyf(zA0), leakyf(zA1));
        *(float2*)&oB[nt * 8 + q * 2] = make_float2(leakyf(zB0), leakyf(zB1));
    }
}

// ============================================================================
extern "C" void kernel_launch(void* const* d_in, const int* in_sizes, int n_in,
                              void* d_out, int out_size) {
    const float* h   = (const float*)d_in[0];
    const int*   adj = (const int*)d_in[1];
    const float* Ww  = (const float*)d_in[2];
    const float* Wb  = (const float*)d_in[3];
    const float* aw  = (const float*)d_in[4];
    float* out = (float*)d_out;

    k_init<<<1, 32>>>();
    k_linear<<<dim3(16, 8), 256>>>(h, Ww, Wb, aw);
    cudaFuncSetAttribute(k_attn, cudaFuncAttributeMaxDynamicSharedMemorySize,
                         ATTN_SMEM);
    k_attn<<<128, 256, ATTN_SMEM>>>(adj, out);
}